// round 8
// baseline (speedup 1.0000x reference)
#include <cuda_runtime.h>
#include <math.h>

// Problem shape (fixed by reference setup_inputs)
#define B    32
#define HW   12544
#define HW64 (HW * 64)        // float4 per batch
#define C    256
#define CR   16

#define NBLK  592             // 4 persistent CTAs per SM (148 * 4) — all resident
#define GROUP 2
#define NGRP  (B / GROUP)     // 16 chip-wide sync intervals

// Scratch (no cudaMalloc allowed); zero-init at load, self-resetting per run
__device__ float        g_sums[B * C];
__device__ unsigned int g_cnt[NGRP];
__device__ unsigned int g_cnt2[NGRP];

// ---------------------------------------------------------------------------
__device__ __forceinline__ void mlp_one_batch(
    int b, int tid, float* s_mean, float (*s_part)[CR], float* s_h,
    float* se_out,
    const float* __restrict__ w1, const float* __restrict__ bb1,
    const float* __restrict__ w2, const float* __restrict__ bb2)
{
    s_mean[tid] = g_sums[b * C + tid] * (1.0f / (float)HW);
    __syncthreads();
    if (tid < 64) {
        int j = tid & 15, part = tid >> 4, c0 = part * 64;
        float acc = 0.0f;
        #pragma unroll 8
        for (int c = c0; c < c0 + 64; c++)
            acc += s_mean[c] * w1[c * CR + j];
        s_part[part][j] = acc;
    }
    __syncthreads();
    if (tid < CR) {
        float acc = bb1[tid] + s_part[0][tid] + s_part[1][tid]
                             + s_part[2][tid] + s_part[3][tid];
        s_h[tid] = fmaxf(acc, 0.0f);
    }
    __syncthreads();
    {
        float acc = bb2[tid];
        #pragma unroll
        for (int j = 0; j < CR; j++)
            acc += s_h[j] * w2[j * C + tid];
        se_out[tid] = 1.0f / (1.0f + __expf(-acc));
    }
    __syncthreads();   // s_mean reused by next batch
}

__global__ __launch_bounds__(256, 4) void se_persist_kernel(
    const float* __restrict__ in,
    const float* __restrict__ w1, const float* __restrict__ bb1,
    const float* __restrict__ w2, const float* __restrict__ bb2,
    float* __restrict__ out)
{
    __shared__ float4 s_redA[256];
    __shared__ float4 s_redB[256];
    __shared__ float  s_mean[C];
    __shared__ float  s_part[4][CR];
    __shared__ float  s_h[CR];
    __shared__ float  s_se[GROUP][C];
    __shared__ int    s_last;

    const int blk  = blockIdx.x;
    const int tid  = threadIdx.x;
    const int qid  = tid & 63;
    const int prow = tid >> 6;

    // position split: blocks 0..111 get 22 positions, rest 21 (sum = 12544)
    const int npos  = 21 + (blk < 112 ? 1 : 0);
    const int start = blk * 21 + min(blk, 112);
    const size_t off = ((size_t)(start + prow)) * 64 + qid;  // + k*256 per step
    const int loc   = prow * 64 + qid;                       // vs bound, + k*256
    const int bound = npos * 64;

    const float4* in4  = reinterpret_cast<const float4*>(in);
    float4*       out4 = reinterpret_cast<float4*>(out);

    #define REDUCE_PUBLISH(gi, nb0, nb1, a0, a1)                              \
    {                                                                          \
        s_redA[tid] = a0; s_redB[tid] = a1;                                    \
        __syncthreads();                                                       \
        if (prow == 0) {                                                       \
            float4 r0 = s_redA[qid],       r1 = s_redA[qid + 64];              \
            float4 r2 = s_redA[qid + 128], r3 = s_redA[qid + 192];             \
            float* dst = &g_sums[(nb0) * C + 4 * qid];                         \
            atomicAdd(dst + 0, r0.x + r1.x + r2.x + r3.x);                     \
            atomicAdd(dst + 1, r0.y + r1.y + r2.y + r3.y);                     \
            atomicAdd(dst + 2, r0.z + r1.z + r2.z + r3.z);                     \
            atomicAdd(dst + 3, r0.w + r1.w + r2.w + r3.w);                     \
            __threadfence();                                                   \
        } else if (prow == 1) {                                                \
            float4 r0 = s_redB[qid],       r1 = s_redB[qid + 64];              \
            float4 r2 = s_redB[qid + 128], r3 = s_redB[qid + 192];             \
            float* dst = &g_sums[(nb1) * C + 4 * qid];                         \
            atomicAdd(dst + 0, r0.x + r1.x + r2.x + r3.x);                     \
            atomicAdd(dst + 1, r0.y + r1.y + r2.y + r3.y);                     \
            atomicAdd(dst + 2, r0.z + r1.z + r2.z + r3.z);                     \
            atomicAdd(dst + 3, r0.w + r1.w + r2.w + r3.w);                     \
            __threadfence();                                                   \
        }                                                                      \
        __syncthreads();                                                       \
        if (tid == 0) { __threadfence(); atomicAdd(&g_cnt[gi], 1u); }          \
    }

    // ---------------- prologue: pool group 0 (batches 0, 1) ----------------
    {
        float4 a0 = make_float4(0.f,0.f,0.f,0.f);
        float4 a1 = make_float4(0.f,0.f,0.f,0.f);
        #pragma unroll
        for (int k = 0; k < 6; k++) {
            if (loc + k * 256 < bound) {
                float4 v0 = in4[(size_t)0 * HW64 + off + k * 256];
                float4 v1 = in4[(size_t)1 * HW64 + off + k * 256];
                a0.x += v0.x; a0.y += v0.y; a0.z += v0.z; a0.w += v0.w;
                a1.x += v1.x; a1.y += v1.y; a1.z += v1.z; a1.w += v1.w;
            }
        }
        REDUCE_PUBLISH(0, 0, 1, a0, a1);
    }

    // ---------------- main loop over 16 groups ----------------
    for (int g = 0; g < NGRP; g++) {
        const int b0 = 2 * g, b1 = 2 * g + 1;

        if (tid == 0) {
            volatile unsigned int* c = &g_cnt[g];
            while (*c < NBLK) { }
            __threadfence();
        }
        __syncthreads();

        mlp_one_batch(b0, tid, s_mean, s_part, s_h, s_se[0], w1, bb1, w2, bb2);
        mlp_one_batch(b1, tid, s_mean, s_part, s_h, s_se[1], w1, bb1, w2, bb2);

        if (tid == 0) {
            unsigned int old = atomicAdd(&g_cnt2[g], 1u);
            s_last = (old == NBLK - 1);
        }
        __syncthreads();
        if (s_last) {
            g_sums[b0 * C + tid] = 0.0f;
            g_sums[b1 * C + tid] = 0.0f;
            if (tid == 0) { g_cnt[g] = 0u; g_cnt2[g] = 0u; }
        }

        const float4 sv0 = *reinterpret_cast<const float4*>(&s_se[0][4 * qid]);
        const float4 sv1 = *reinterpret_cast<const float4*>(&s_se[1][4 * qid]);

        const size_t c0 = (size_t)b0 * HW64 + off;
        const size_t c1 = (size_t)b1 * HW64 + off;

        if (g + 1 < NGRP) {
            const int nb0 = b0 + 2, nb1 = b1 + 2;
            const size_t n0 = (size_t)nb0 * HW64 + off;
            const size_t n1 = (size_t)nb1 * HW64 + off;
            float4 a0 = make_float4(0.f,0.f,0.f,0.f);
            float4 a1 = make_float4(0.f,0.f,0.f,0.f);
            #pragma unroll
            for (int k = 0; k < 6; k++) {
                if (loc + k * 256 < bound) {
                    float4 p0 = in4[n0 + k * 256];
                    float4 p1 = in4[n1 + k * 256];
                    float4 v0 = __ldcs(&in4[c0 + k * 256]);
                    float4 v1 = __ldcs(&in4[c1 + k * 256]);
                    a0.x += p0.x; a0.y += p0.y; a0.z += p0.z; a0.w += p0.w;
                    a1.x += p1.x; a1.y += p1.y; a1.z += p1.z; a1.w += p1.w;
                    v0.x *= sv0.x; v0.y *= sv0.y; v0.z *= sv0.z; v0.w *= sv0.w;
                    v1.x *= sv1.x; v1.y *= sv1.y; v1.z *= sv1.z; v1.w *= sv1.w;
                    __stcs(&out4[c0 + k * 256], v0);
                    __stcs(&out4[c1 + k * 256], v1);
                }
            }
            REDUCE_PUBLISH(g + 1, nb0, nb1, a0, a1);
        } else {
            #pragma unroll
            for (int k = 0; k < 6; k++) {
                if (loc + k * 256 < bound) {
                    float4 v0 = __ldcs(&in4[c0 + k * 256]);
                    float4 v1 = __ldcs(&in4[c1 + k * 256]);
                    v0.x *= sv0.x; v0.y *= sv0.y; v0.z *= sv0.z; v0.w *= sv0.w;
                    v1.x *= sv1.x; v1.y *= sv1.y; v1.z *= sv1.z; v1.w *= sv1.w;
                    __stcs(&out4[c0 + k * 256], v0);
                    __stcs(&out4[c1 + k * 256], v1);
                }
            }
        }
    }
    #undef REDUCE_PUBLISH
}

// ---------------------------------------------------------------------------
extern "C" void kernel_launch(void* const* d_in, const int* in_sizes, int n_in,
                              void* d_out, int out_size)
{
    const float* in = (const float*)d_in[0];
    const float* w1 = (const float*)d_in[1];
    const float* b1 = (const float*)d_in[2];
    const float* w2 = (const float*)d_in[3];
    const float* b2 = (const float*)d_in[4];
    float* out = (float*)d_out;

    se_persist_kernel<<<NBLK, 256>>>(in, w1, b1, w2, b2, out);
}

// round 10
// speedup vs baseline: 2.1419x; 2.1419x over previous
#include <cuda_runtime.h>
#include <math.h>

// Problem shape (fixed by reference setup_inputs)
#define B     32
#define HW    12544
#define C     256
#define CR    16

#define GROUP 4               // batches per phase group (51.4 MB < L2)
#define NGRP  (B / GROUP)     // 8 groups -> 9 phases
#define SPL   98              // chunks per batch
#define CPOS  128             // positions per chunk (98*128 = 12544)
#define GB    (GROUP * SPL)   // 392 blocks per role
#define PF    8               // prefetch depth for scale role

// Scratch (no cudaMalloc); zero-init at load, self-resetting each run
__device__ __align__(16) float        g_sums[B * C];
__device__ __align__(16) float        g_se[B * C];
__device__               unsigned int g_cnt[B];

// ---------------------------------------------------------------------------
// Phase kernel. Blocks [0,GB): pool group p (skip if p==NGRP).
//               Blocks [GB,2GB): scale group p-1 from L2 (skip if p==0).
// ---------------------------------------------------------------------------
__global__ __launch_bounds__(256) void se_phase_kernel(
    int p,
    const float* __restrict__ in,
    const float* __restrict__ w1, const float* __restrict__ bb1,
    const float* __restrict__ w2, const float* __restrict__ bb2,
    float* __restrict__ out)
{
    const int tid  = threadIdx.x;
    const int qid  = tid & 63;
    const int prow = tid >> 6;

    const float4* in4  = reinterpret_cast<const float4*>(in);
    float4*       out4 = reinterpret_cast<float4*>(out);

    if (blockIdx.x < GB) {
        // ------------------------- POOL role -------------------------
        if (p == NGRP) return;
        const int b = GROUP * p + blockIdx.x / SPL;
        const int s = blockIdx.x % SPL;

        const size_t base = ((size_t)b * HW + s * CPOS + prow) * 64 + qid;

        float4 a0 = make_float4(0.f, 0.f, 0.f, 0.f);
        float4 a1 = make_float4(0.f, 0.f, 0.f, 0.f);
        #pragma unroll 8
        for (int k = 0; k < 32; k += 2) {
            float4 v0 = in4[base + (size_t)k * 256];
            float4 v1 = in4[base + (size_t)(k + 1) * 256];
            a0.x += v0.x; a0.y += v0.y; a0.z += v0.z; a0.w += v0.w;
            a1.x += v1.x; a1.y += v1.y; a1.z += v1.z; a1.w += v1.w;
        }
        a0.x += a1.x; a0.y += a1.y; a0.z += a1.z; a0.w += a1.w;

        __shared__ __align__(16) float4 s_red[256];
        __shared__ int s_last;
        s_red[tid] = a0;
        __syncthreads();
        if (prow == 0) {
            float4 r0 = s_red[qid],       r1 = s_red[qid + 64];
            float4 r2 = s_red[qid + 128], r3 = s_red[qid + 192];
            float* dst = &g_sums[b * C + 4 * qid];
            atomicAdd(dst + 0, r0.x + r1.x + r2.x + r3.x);
            atomicAdd(dst + 1, r0.y + r1.y + r2.y + r3.y);
            atomicAdd(dst + 2, r0.z + r1.z + r2.z + r3.z);
            atomicAdd(dst + 3, r0.w + r1.w + r2.w + r3.w);
            __threadfence();
        }
        __syncthreads();
        if (tid == 0) {
            __threadfence();
            unsigned int old = atomicAdd(&g_cnt[b], 1u);
            s_last = (old == SPL - 1);
            if (s_last) g_cnt[b] = 0u;   // self-reset for next graph replay
        }
        __syncthreads();
        if (!s_last) return;
        __threadfence();   // acquire: all blocks' atomics visible

        // ---- last block of batch b: tiny MLP -> g_se[b], reset sums ----
        __shared__ __align__(16) float s_mean[C];
        __shared__ float s_part[4][CR];
        __shared__ float s_h[CR];

        s_mean[tid] = g_sums[b * C + tid] * (1.0f / (float)HW);
        g_sums[b * C + tid] = 0.0f;      // reset for next replay
        __syncthreads();
        if (tid < 64) {
            int j = tid & 15, part = tid >> 4, c0 = part * 64;
            float acc = 0.0f;
            #pragma unroll 8
            for (int c = c0; c < c0 + 64; c++)
                acc += s_mean[c] * w1[c * CR + j];
            s_part[part][j] = acc;
        }
        __syncthreads();
        if (tid < CR) {
            float acc = bb1[tid] + s_part[0][tid] + s_part[1][tid]
                                 + s_part[2][tid] + s_part[3][tid];
            s_h[tid] = fmaxf(acc, 0.0f);
        }
        __syncthreads();
        {
            float acc = bb2[tid];
            #pragma unroll
            for (int j = 0; j < CR; j++)
                acc += s_h[j] * w2[j * C + tid];
            g_se[b * C + tid] = 1.0f / (1.0f + __expf(-acc));
        }
    } else {
        // ------------------------- SCALE role -------------------------
        if (p == 0) return;
        const int blk = blockIdx.x - GB;
        const int b = GROUP * (p - 1) + blk / SPL;
        const int s = blk % SPL;

        const size_t base = ((size_t)b * HW + s * CPOS + prow) * 64 + qid;

        // prefetch first (loads fly while we fetch g_se)
        float4 pf[PF];
        #pragma unroll
        for (int k = 0; k < PF; k++)
            pf[k] = in4[base + (size_t)k * 256];

        __shared__ __align__(16) float s_se[C];
        s_se[tid] = g_se[b * C + tid];   // written last phase (kernel boundary)
        __syncthreads();
        const float4 sv = *reinterpret_cast<const float4*>(&s_se[4 * qid]);

        #pragma unroll
        for (int k = 0; k < PF; k++) {
            float4 v = pf[k];
            v.x *= sv.x; v.y *= sv.y; v.z *= sv.z; v.w *= sv.w;
            __stcs(&out4[base + (size_t)k * 256], v);
        }
        #pragma unroll 8
        for (int k = PF; k < 32; k++) {
            float4 v = in4[base + (size_t)k * 256];   // L2 hit (pooled last phase)
            v.x *= sv.x; v.y *= sv.y; v.z *= sv.z; v.w *= sv.w;
            __stcs(&out4[base + (size_t)k * 256], v);
        }
    }
}

// ---------------------------------------------------------------------------
extern "C" void kernel_launch(void* const* d_in, const int* in_sizes, int n_in,
                              void* d_out, int out_size)
{
    const float* in = (const float*)d_in[0];
    const float* w1 = (const float*)d_in[1];
    const float* b1 = (const float*)d_in[2];
    const float* w2 = (const float*)d_in[3];
    const float* b2 = (const float*)d_in[4];
    float* out = (float*)d_out;

    for (int p = 0; p <= NGRP; p++)
        se_phase_kernel<<<2 * GB, 256>>>(p, in, w1, b1, w2, b2, out);
}